// round 6
// baseline (speedup 1.0000x reference)
#include <cuda_runtime.h>
#include <cuda_bf16.h>

// Problem: DotProductAttention_83476984365340
// softmax over singleton axis == 1.0 -> output = values.sum(axis=1).
// Pure HBM-bound column sum of values [32, 4096, 1024] f32 (512 MiB read).
//
// Stream-count sweep (ncu dur / achieved HBM):
//   1184 CTAs (8.0/SM): 86.1us, 6.31 TB/s
//   1024 CTAs (6.9/SM): 84.6us, 6.38 TB/s
//    512 CTAs (3.5/SM): 81.9us, 6.61 TB/s
//    256 CTAs (1.7/SM): 78.9us, 6.86 TB/s
// Monotone: fewer concurrent streams per SM => higher DRAM efficiency.
// R6: the limit point — grid = 148 = EXACTLY 1 CTA/SM, one ~3.46 MiB
//     contiguous stream each (885/886 rows of the flattened [B*T, D] space).
//     Segmented inner loop flushes atomics at batch boundaries (<=1 cross/CTA).

#define B_DIM 32
#define T_DIM 4096
#define D_DIM 1024
#define NUM_SMS 148
#define TOTAL_ROWS (B_DIM * T_DIM)          // 131072
#define THREADS 256                          // 256 threads * float4 = 1024 = D
#define BATCH 16

__global__ __launch_bounds__(THREADS, 1)
void values_colsum_kernel(const float* __restrict__ values, float* __restrict__ out)
{
    const int cta = blockIdx.x;              // 0..147
    const int d4  = threadIdx.x;             // float4 lane within row (0..255)

    // Balanced contiguous row range over the flattened [B*T] space.
    const int r0 = (int)(((long long)cta * TOTAL_ROWS) / NUM_SMS);
    const int r1 = (int)(((long long)(cta + 1) * TOTAL_ROWS) / NUM_SMS);

    const float4* __restrict__ p =
        reinterpret_cast<const float4*>(values) + (size_t)r0 * (D_DIM / 4) + d4;

    int r = r0;
    while (r < r1) {
        const int b = r >> 12;                       // r / T_DIM
        int seg_end = (b + 1) << 12;                 // next batch boundary
        if (seg_end > r1) seg_end = r1;
        const int nrows = seg_end - r;

        float4 acc0 = make_float4(0.f, 0.f, 0.f, 0.f);
        float4 acc1 = make_float4(0.f, 0.f, 0.f, 0.f);

        const int nbatched = nrows & ~(BATCH - 1);

        for (int it = 0; it < nbatched; it += BATCH) {
            // Front-batch BATCH independent 128-bit loads -> deep MLP.
            // 16 rows * 4KB = 64KB contiguous per CTA iteration.
            float4 v[BATCH];
            #pragma unroll
            for (int k = 0; k < BATCH; ++k)
                v[k] = p[(size_t)k * (D_DIM / 4)];
            p += (size_t)BATCH * (D_DIM / 4);

            #pragma unroll
            for (int k = 0; k < BATCH; k += 2) {
                acc0.x += v[k].x;   acc0.y += v[k].y;
                acc0.z += v[k].z;   acc0.w += v[k].w;
                acc1.x += v[k+1].x; acc1.y += v[k+1].y;
                acc1.z += v[k+1].z; acc1.w += v[k+1].w;
            }
        }

        // Remainder rows of this segment.
        for (int k = nbatched; k < nrows; ++k) {
            float4 v = *p;
            p += (D_DIM / 4);
            acc0.x += v.x; acc0.y += v.y; acc0.z += v.z; acc0.w += v.w;
        }

        acc0.x += acc1.x; acc0.y += acc1.y;
        acc0.z += acc1.z; acc0.w += acc1.w;

        float* o = out + (size_t)b * D_DIM + d4 * 4;
        atomicAdd(o + 0, acc0.x);
        atomicAdd(o + 1, acc0.y);
        atomicAdd(o + 2, acc0.z);
        atomicAdd(o + 3, acc0.w);

        r = seg_end;
    }
}

extern "C" void kernel_launch(void* const* d_in, const int* in_sizes, int n_in,
                              void* d_out, int out_size)
{
    // Input order per reference setup_inputs(): query, keys, values, W
    const float* values = (const float*)d_in[2];
    float* out = (float*)d_out;

    cudaMemsetAsync(out, 0, (size_t)out_size * sizeof(float));

    values_colsum_kernel<<<NUM_SMS, THREADS>>>(values, out);
}

// round 7
// speedup vs baseline: 1.0479x; 1.0479x over previous
#include <cuda_runtime.h>
#include <cuda_bf16.h>

// Problem: DotProductAttention_83476984365340
// softmax over singleton axis == 1.0 -> output = values.sum(axis=1).
// Pure HBM-bound column sum of values [32, 4096, 1024] f32 (512 MiB read).
//
// Stream-count sweep (ncu dur / achieved HBM):
//   1184 CTAs (8.0/SM): 86.1us, 6.31 TB/s
//   1024 CTAs (6.9/SM): 84.6us, 6.38 TB/s
//    512 CTAs (3.5/SM): 81.9us, 6.61 TB/s
//    256 CTAs (1.7/SM): 78.9us, 6.86 TB/s   <- best, but 40 SMs idle half the run
//    148 CTAs (1.0/SM): 84.6us, 6.39 TB/s   <- under-saturated (in-flight too low)
// Optimum ~2 streams/SM. R7: grid = 296 = EXACTLY 2 CTAs per SM, balanced
// split of flattened [B*T] rows (442/443 rows/CTA), uniform load, ~4.8MB in flight.

#define B_DIM 32
#define T_DIM 4096
#define D_DIM 1024
#define NUM_CTAS 296                          // 2 per SM on 148 SMs
#define TOTAL_ROWS (B_DIM * T_DIM)           // 131072
#define THREADS 256                           // 256 threads * float4 = 1024 = D
#define BATCH 16

__global__ __launch_bounds__(THREADS, 2)
void values_colsum_kernel(const float* __restrict__ values, float* __restrict__ out)
{
    const int cta = blockIdx.x;               // 0..295
    const int d4  = threadIdx.x;              // float4 lane within row (0..255)

    // Balanced contiguous row range over the flattened [B*T] space.
    const int r0 = (int)(((long long)cta * TOTAL_ROWS) / NUM_CTAS);
    const int r1 = (int)(((long long)(cta + 1) * TOTAL_ROWS) / NUM_CTAS);

    const float4* __restrict__ p =
        reinterpret_cast<const float4*>(values) + (size_t)r0 * (D_DIM / 4) + d4;

    int r = r0;
    while (r < r1) {
        const int b = r >> 12;                       // r / T_DIM
        int seg_end = (b + 1) << 12;                 // next batch boundary
        if (seg_end > r1) seg_end = r1;
        const int nrows = seg_end - r;

        float4 acc0 = make_float4(0.f, 0.f, 0.f, 0.f);
        float4 acc1 = make_float4(0.f, 0.f, 0.f, 0.f);

        const int nbatched = nrows & ~(BATCH - 1);

        for (int it = 0; it < nbatched; it += BATCH) {
            // Front-batch BATCH independent 128-bit loads -> deep MLP.
            // 16 consecutive rows * 4KB = 64KB contiguous per iteration.
            float4 v[BATCH];
            #pragma unroll
            for (int k = 0; k < BATCH; ++k)
                v[k] = p[(size_t)k * (D_DIM / 4)];
            p += (size_t)BATCH * (D_DIM / 4);

            #pragma unroll
            for (int k = 0; k < BATCH; k += 2) {
                acc0.x += v[k].x;   acc0.y += v[k].y;
                acc0.z += v[k].z;   acc0.w += v[k].w;
                acc1.x += v[k+1].x; acc1.y += v[k+1].y;
                acc1.z += v[k+1].z; acc1.w += v[k+1].w;
            }
        }

        // Remainder rows of this segment.
        for (int k = nbatched; k < nrows; ++k) {
            float4 v = *p;
            p += (D_DIM / 4);
            acc0.x += v.x; acc0.y += v.y; acc0.z += v.z; acc0.w += v.w;
        }

        acc0.x += acc1.x; acc0.y += acc1.y;
        acc0.z += acc1.z; acc0.w += acc1.w;

        float* o = out + (size_t)b * D_DIM + d4 * 4;
        atomicAdd(o + 0, acc0.x);
        atomicAdd(o + 1, acc0.y);
        atomicAdd(o + 2, acc0.z);
        atomicAdd(o + 3, acc0.w);

        r = seg_end;
    }
}

extern "C" void kernel_launch(void* const* d_in, const int* in_sizes, int n_in,
                              void* d_out, int out_size)
{
    // Input order per reference setup_inputs(): query, keys, values, W
    const float* values = (const float*)d_in[2];
    float* out = (float*)d_out;

    cudaMemsetAsync(out, 0, (size_t)out_size * sizeof(float));

    values_colsum_kernel<<<NUM_CTAS, THREADS>>>(values, out);
}

// round 8
// speedup vs baseline: 1.0695x; 1.0207x over previous
#include <cuda_runtime.h>
#include <cuda_bf16.h>

// Problem: DotProductAttention_83476984365340
// softmax over singleton axis == 1.0 -> output = values.sum(axis=1).
// Pure HBM-bound column sum of values [32, 4096, 1024] f32 (512 MiB read).
//
// Stream-count sweep (ncu dur / achieved HBM):
//   148 CTAs: 84.6us 6.39 | 256: 78.9us 6.86 <- best | 296: 81.2us 6.67
//   512: 81.9us 6.61 | 1024: 84.6us 6.38 | 1184: 86.1us 6.31
// Optimum: 256 CTAs (1.7/SM), 2MiB ALIGNED contiguous stream per CTA.
// R8 = R5 grid/layout + software-pipelined double-buffered loads (8-deep):
// loads for iteration i+1 issue before consuming iteration i, keeping each
// warp's LSU occupancy continuous instead of 16-load bursts.

#define B_DIM 32
#define T_DIM 4096
#define D_DIM 1024
#define CHUNKS_PER_B 8
#define T_PER_CHUNK (T_DIM / CHUNKS_PER_B)  // 512 rows = 2 MiB per CTA
#define THREADS 256                          // 256 threads * float4 = 1024 = D
#define PIPE 8                               // double-buffer depth

__global__ __launch_bounds__(THREADS, 2)
void values_colsum_kernel(const float* __restrict__ values, float* __restrict__ out)
{
    const int b  = blockIdx.y;                 // 0..31
    const int c  = blockIdx.x;                 // 0..7
    const int d4 = threadIdx.x;                // float4 lane within row (0..255)

    const float4* __restrict__ p =
        reinterpret_cast<const float4*>(values) +
        (size_t)b * T_DIM * (D_DIM / 4) +
        (size_t)c * T_PER_CHUNK * (D_DIM / 4) +
        d4;

    float4 acc0 = make_float4(0.f, 0.f, 0.f, 0.f);
    float4 acc1 = make_float4(0.f, 0.f, 0.f, 0.f);

    // Prologue: fill buffer A.
    float4 va[PIPE], vb[PIPE];
    #pragma unroll
    for (int k = 0; k < PIPE; ++k)
        va[k] = p[(size_t)k * (D_DIM / 4)];
    p += (size_t)PIPE * (D_DIM / 4);

    // Steady state: 512 rows = 64 groups of 8; prologue consumed 1 group,
    // loop runs 63 iterations alternating buffers, epilogue drains the last.
    const int ITERS = T_PER_CHUNK / PIPE - 1;  // 63

    for (int it = 0; it < ITERS; ++it) {
        float4* cur  = (it & 1) ? vb : va;
        float4* next = (it & 1) ? va : vb;

        // Issue next group's loads BEFORE consuming current group.
        #pragma unroll
        for (int k = 0; k < PIPE; ++k)
            next[k] = p[(size_t)k * (D_DIM / 4)];
        p += (size_t)PIPE * (D_DIM / 4);

        #pragma unroll
        for (int k = 0; k < PIPE; k += 2) {
            acc0.x += cur[k].x;   acc0.y += cur[k].y;
            acc0.z += cur[k].z;   acc0.w += cur[k].w;
            acc1.x += cur[k+1].x; acc1.y += cur[k+1].y;
            acc1.z += cur[k+1].z; acc1.w += cur[k+1].w;
        }
    }

    // Epilogue: drain the final buffer (ITERS=63 is odd -> last filled is vb).
    {
        float4* cur = (ITERS & 1) ? vb : va;
        #pragma unroll
        for (int k = 0; k < PIPE; k += 2) {
            acc0.x += cur[k].x;   acc0.y += cur[k].y;
            acc0.z += cur[k].z;   acc0.w += cur[k].w;
            acc1.x += cur[k+1].x; acc1.y += cur[k+1].y;
            acc1.z += cur[k+1].z; acc1.w += cur[k+1].w;
        }
    }

    acc0.x += acc1.x; acc0.y += acc1.y; acc0.z += acc1.z; acc0.w += acc1.w;

    float* o = out + (size_t)b * D_DIM + d4 * 4;
    atomicAdd(o + 0, acc0.x);
    atomicAdd(o + 1, acc0.y);
    atomicAdd(o + 2, acc0.z);
    atomicAdd(o + 3, acc0.w);
}

extern "C" void kernel_launch(void* const* d_in, const int* in_sizes, int n_in,
                              void* d_out, int out_size)
{
    // Input order per reference setup_inputs(): query, keys, values, W
    const float* values = (const float*)d_in[2];
    float* out = (float*)d_out;

    cudaMemsetAsync(out, 0, (size_t)out_size * sizeof(float));

    dim3 grid(CHUNKS_PER_B, B_DIM);
    values_colsum_kernel<<<grid, THREADS>>>(values, out);
}